// round 17
// baseline (speedup 1.0000x reference)
#include <cuda_runtime.h>
#include <cuda_fp16.h>

// WeightedDiceLoss (sm_103a) — 2-col × 2-row vectorized consumer (float2 LDG,
// half2 LDS), fp16 swizzled ring RING=96, 4 mainloop barriers, prefetched
// producer, fully static ring addressing.
// weight = 1 + 5*|boxavg31(target) - target|, zero pad, /961
// out = 1 - (2*sum(in*t*w) + 1) / (sum(in*w) + sum(t*w) + 1)

#define Wd    512
#define Hd    512
#define Rr    128
#define HALO  15
#define SLABR (Rr + 2*HALO)        // 158
#define RING  96                   // fp16 rows of 1KB -> 96KB
#define INV_KK2 (1.0f/961.0f)

__device__ float g_part[3 * 1024];
__device__ unsigned int g_count = 0;

// Ring access for row (R0 + h), R0 compile-time, h in {0,1} runtime.
// qoff = qb + h*1024. Slot = (R0+h) % 96; folds statically except R0==95.
__device__ __forceinline__ const __half2* ringAt(const char* HSb, int R0,
                                                 int h, int qoff, int qb) {
    if (R0 == 95) return (const __half2*)(HSb + (h ? 0 : 95 * 1024) + qb);
    const int s0 = (R0 < RING) ? R0 : R0 - RING;
    return (const __half2*)(HSb + s0 * 1024 + qoff);
}

__global__ __launch_bounds__(512, 2)
void wdice_main(const float* __restrict__ input,
                const float* __restrict__ target,
                float* __restrict__ out)
{
    extern __shared__ __half HS[];          // [RING][512] swizzled fp16 hsum
    const int tid  = threadIdx.x;
    const int wid  = tid >> 5;
    const int lane = tid & 31;
    const int img  = blockIdx.x >> 2;       // 4 slabs per image
    const int slab = blockIdx.x & 3;
    const int r0   = slab * Rr;
    const size_t imgOff = (size_t)img * (size_t)(Hd * Wd);

    // ---- Producer helpers (unchanged from R16) ----
    auto pref = [&](int prRow, float v[16]) {
        const int j  = prRow + wid;
        const int gr = r0 - HALO + j;
        if (j < SLABR && gr >= 0 && gr < Hd) {
            const float4* row = (const float4*)(target + imgOff + (size_t)gr * Wd);
            #pragma unroll
            for (int q = 0; q < 4; q++) {
                float4 f = row[lane * 4 + q];
                v[4*q+0] = f.x; v[4*q+1] = f.y; v[4*q+2] = f.z; v[4*q+3] = f.w;
            }
        } else {
            #pragma unroll
            for (int i = 0; i < 16; i++) v[i] = 0.f;
        }
    };
    auto scanStore = [&](int prSlot, float p[16]) {
        uint4* dstRow = (uint4*)((char*)HS + (size_t)(prSlot + wid) * 1024);
        const int key = (lane >> 2) & 7;
        #pragma unroll
        for (int i = 1; i < 16; i++) p[i] += p[i-1];
        const float T  = p[15];
        float Tp = __shfl_up_sync(0xffffffffu, T, 1);
        if (lane == 0) Tp = 0.f;
        const float base = Tp + T;
        float h[16];
        #pragma unroll
        for (int i = 0; i < 16; i++) {
            float pm = __shfl_up_sync(0xffffffffu, p[i], 1);
            if (lane == 0) pm = 0.f;
            h[i] = base - pm;
        }
        #pragma unroll
        for (int i = 1; i < 16; i++) {
            float pp = __shfl_down_sync(0xffffffffu, p[i-1], 1);
            if (lane == 31) pp = 0.f;
            h[i] += pp;
        }
        unsigned up[8];
        #pragma unroll
        for (int q = 0; q < 8; q++) {
            __half2 hh = __floats2half2_rn(h[2*q], h[2*q+1]);
            up[q] = *reinterpret_cast<unsigned*>(&hh);
        }
        dstRow[(2 * lane)     ^ key] = make_uint4(up[0], up[1], up[2], up[3]);
        dstRow[(2 * lane + 1) ^ key] = make_uint4(up[4], up[5], up[6], up[7]);
    };

    // ---- Prime ring rows 0..95 (two-buffer LDG/scan overlap).
    float pw[16];
    {
        float pa[16];
        pref(0,  pa); pref(16, pw);
        scanStore(0,  pa); pref(32, pa);
        scanStore(16, pw); pref(48, pw);
        scanStore(32, pa); pref(64, pa);
        scanStore(48, pw); pref(80, pw);
        scanStore(64, pa);
        scanStore(80, pw);
    }
    __syncthreads();                                   // BAR0

    // ---- Consumer: thread owns column pair (2p, 2p+1), row phase hph.
    const int p   = tid & 255;
    const int hph = tid >> 8;                          // 0 = even rows, 1 = odd
    const int uu  = p >> 2;
    const int qb  = (uu ^ ((uu >> 3) & 7)) * 16 + (p & 3) * 4;
    const int qoff = qb + hph * 1024;
    const char* HSb = (const char*)HS;

    float2 vs = make_float2(0.f, 0.f);
    #pragma unroll
    for (int j = 0; j <= 2 * HALO; j++) {              // rows (j+hph), j=0..30
        float2 a = __half22float2(*ringAt(HSb, j, hph, qoff, qb));
        vs.x += a.x; vs.y += a.y;
    }

    float2 aI = make_float2(0.f, 0.f);
    float2 aA = make_float2(0.f, 0.f);
    float2 aB = make_float2(0.f, 0.f);
    const float2* tgt2 = (const float2*)(target + imgOff + (size_t)r0 * Wd) + p;
    const float2* inp2 = (const float2*)(input  + imgOff + (size_t)r0 * Wd) + p;

    // One iteration: row s_+hph (2 cols); advance window by 2 rows.
#define CITER(CH, kk) { \
        const int s_ = 16 * (CH) + 2 * (kk); \
        const float2 t2 = tgt2[(s_) * 256 + hph * 256]; \
        const float2 i2 = inp2[(s_) * 256 + hph * 256]; \
        const float w0 = fmaf(5.f, fabsf(fmaf(vs.x, INV_KK2, -t2.x)), 1.f); \
        const float w1 = fmaf(5.f, fabsf(fmaf(vs.y, INV_KK2, -t2.y)), 1.f); \
        const float tw0 = t2.x * w0, tw1 = t2.y * w1; \
        aI.x = fmaf(i2.x, tw0, aI.x);  aI.y = fmaf(i2.y, tw1, aI.y); \
        aA.x = fmaf(i2.x, w0,  aA.x);  aA.y = fmaf(i2.y, w1,  aA.y); \
        aB.x += tw0;                   aB.y += tw1; \
        if (!((CH) == 7 && (kk) == 7)) { \
            float2 A0 = __half22float2(*ringAt(HSb, s_ + 31, hph, qoff, qb)); \
            float2 A1 = __half22float2(*ringAt(HSb, s_ + 32, hph, qoff, qb)); \
            float2 S0 = __half22float2(*ringAt(HSb, s_,      hph, qoff, qb)); \
            float2 S1 = __half22float2(*ringAt(HSb, s_ + 1,  hph, qoff, qb)); \
            vs.x += (A0.x + A1.x) - (S0.x + S1.x); \
            vs.y += (A0.y + A1.y) - (S0.y + S1.y); \
        } }

#define CONSUME(CH) { \
        CITER(CH,0) CITER(CH,1) CITER(CH,2) CITER(CH,3) \
        CITER(CH,4) CITER(CH,5) CITER(CH,6) CITER(CH,7) }

    // Pipelined schedule (RAW/WAR verified incl. new max-read 16CH+47):
    pref(96, pw);
    CONSUME(0); CONSUME(1);
    __syncthreads();                                   // BAR1
    scanStore(0, pw);  pref(112, pw);
    CONSUME(2);
    scanStore(16, pw); pref(128, pw);
    CONSUME(3);
    __syncthreads();                                   // BAR2
    scanStore(32, pw); pref(144, pw);
    CONSUME(4);
    scanStore(48, pw);
    CONSUME(5);
    __syncthreads();                                   // BAR3
    CONSUME(6); CONSUME(7);

    float rI = aI.x + aI.y, rA = aA.x + aA.y, rB = aB.x + aB.y;

    // ---- Block reduction (fixed order -> deterministic)
    #pragma unroll
    for (int o = 16; o > 0; o >>= 1) {
        rI += __shfl_down_sync(0xffffffffu, rI, o);
        rA += __shfl_down_sync(0xffffffffu, rA, o);
        rB += __shfl_down_sync(0xffffffffu, rB, o);
    }
    __syncthreads();
    float* red = (float*)HS;
    if (lane == 0) { red[wid] = rI; red[16 + wid] = rA; red[32 + wid] = rB; }
    __syncthreads();
    __shared__ unsigned int sIsLast;
    if (tid == 0) {
        float I = 0.f, A = 0.f, B = 0.f;
        #pragma unroll
        for (int i = 0; i < 16; i++) { I += red[i]; A += red[16 + i]; B += red[32 + i]; }
        g_part[blockIdx.x * 3 + 0] = I;
        g_part[blockIdx.x * 3 + 1] = A;
        g_part[blockIdx.x * 3 + 2] = B;
        __threadfence();
        sIsLast = (atomicAdd(&g_count, 1u) == gridDim.x - 1u);
    }
    __syncthreads();

    if (sIsLast) {
        const int nbk = gridDim.x;
        float i = 0.f, a = 0.f, b = 0.f;
        for (int j = tid; j < nbk; j += 512) {
            i += g_part[3 * j + 0];
            a += g_part[3 * j + 1];
            b += g_part[3 * j + 2];
        }
        #pragma unroll
        for (int o = 16; o > 0; o >>= 1) {
            i += __shfl_down_sync(0xffffffffu, i, o);
            a += __shfl_down_sync(0xffffffffu, a, o);
            b += __shfl_down_sync(0xffffffffu, b, o);
        }
        __syncthreads();
        if (lane == 0) { red[wid] = i; red[16 + wid] = a; red[32 + wid] = b; }
        __syncthreads();
        if (tid == 0) {
            float I = 0.f, A = 0.f, B = 0.f;
            #pragma unroll
            for (int q = 0; q < 16; q++) { I += red[q]; A += red[16 + q]; B += red[32 + q]; }
            out[0] = 1.f - (2.f * I + 1.f) / (A + B + 1.f);
            g_count = 0;
        }
    }
}

extern "C" void kernel_launch(void* const* d_in, const int* in_sizes, int n_in,
                              void* d_out, int out_size)
{
    const float* input  = (const float*)d_in[0];
    const float* target = (const float*)d_in[1];
    const int nImg = in_sizes[0] / (Hd * Wd);
    const int grid = nImg * (Hd / Rr);              // 256
    const size_t smem = (size_t)RING * Wd * sizeof(__half);   // 98304 B

    cudaFuncSetAttribute(wdice_main,
                         cudaFuncAttributeMaxDynamicSharedMemorySize, (int)smem);
    wdice_main<<<grid, 512, smem>>>(input, target, (float*)d_out);
}